// round 12
// baseline (speedup 1.0000x reference)
#include <cuda_runtime.h>
#include <cstdint>

#define BATCH  32
#define HW     3136
#define C      256
#define CR     64
#define PPC    16            // pixels per chunk
#define CHUNKS 196           // HW / PPC
#define NG     32            // channel groups of 8 floats (C/8)

// Scratch (allocation-free per harness rules)
__device__ float g_partial[BATCH * CHUNKS * C];
__device__ float g_gate[BATCH * C];

// 256-bit load, pin line in L2 (evict_last)
__device__ __forceinline__ void ld256_evict_last(const float* p, uint32_t* u) {
    asm volatile("ld.global.nc.L2::evict_last.v8.b32 {%0,%1,%2,%3,%4,%5,%6,%7}, [%8];"
                 : "=r"(u[0]), "=r"(u[1]), "=r"(u[2]), "=r"(u[3]),
                   "=r"(u[4]), "=r"(u[5]), "=r"(u[6]), "=r"(u[7])
                 : "l"(p));
}
// 256-bit plain load (normal policy — L2 hits promote)
__device__ __forceinline__ void ld256(const float* p, uint32_t* u) {
    asm volatile("ld.global.nc.v8.b32 {%0,%1,%2,%3,%4,%5,%6,%7}, [%8];"
                 : "=r"(u[0]), "=r"(u[1]), "=r"(u[2]), "=r"(u[3]),
                   "=r"(u[4]), "=r"(u[5]), "=r"(u[6]), "=r"(u[7])
                 : "l"(p));
}

// ---------------------------------------------------------------------------
// gap_kernel: R9's fastest geometry (18.9us, 5.7TB/s). grid = (CHUNKS, BATCH)
// = 6272 blocks, 256 threads. evict_last loads pin x in L2 for mul_kernel.
// Partials stored with __stcs so they don't displace pinned x lines.
// ---------------------------------------------------------------------------
__global__ __launch_bounds__(256) void gap_kernel(const float* __restrict__ x)
{
    const int chunk = blockIdx.x;
    const int b     = blockIdx.y;
    const int tid   = threadIdx.x;
    const int c8    = tid & (NG - 1);
    const int pr    = tid >> 5;

    const float* xp = x + ((size_t)(b * HW + chunk * PPC + pr)) * C + c8 * 8;

    uint32_t u0[8], u1[8];
    ld256_evict_last(xp,                 u0);
    ld256_evict_last(xp + (size_t)8 * C, u1);

    __shared__ float red[8 * C];       // 8KB
    float* rp = &red[pr * C + c8 * 8];
#pragma unroll
    for (int k = 0; k < 8; ++k) {
        rp[k] = __uint_as_float(u0[k]) + __uint_as_float(u1[k]);
    }
    __syncthreads();

    float p0 = 0.0f;
#pragma unroll
    for (int g = 0; g < 8; ++g) {
        p0 += red[g * C + tid];
    }
    __stcs(&g_partial[(b * CHUNKS + chunk) * C + tid], p0);
}

// ---------------------------------------------------------------------------
// fc_kernel: 32 blocks x 256 threads. 4-way accumulate over 196 partials,
// then squeeze->relu6->excite->hsigmoid -> gate.
// ---------------------------------------------------------------------------
__global__ __launch_bounds__(256) void fc_kernel(const float* __restrict__ w1,
                                                 const float* __restrict__ w2)
{
    const int b = blockIdx.x;
    const int t = threadIdx.x;

    __shared__ float s[C];
    __shared__ float h[CR];

    float s0 = 0.f, s1 = 0.f, s2 = 0.f, s3 = 0.f;
#pragma unroll
    for (int k = 0; k < CHUNKS; k += 4) {
        s0 += __ldcs(&g_partial[(b * CHUNKS + k + 0) * C + t]);
        s1 += __ldcs(&g_partial[(b * CHUNKS + k + 1) * C + t]);
        s2 += __ldcs(&g_partial[(b * CHUNKS + k + 2) * C + t]);
        s3 += __ldcs(&g_partial[(b * CHUNKS + k + 3) * C + t]);
    }
    s[t] = ((s0 + s1) + (s2 + s3)) * (1.0f / (float)HW);
    __syncthreads();

    if (t < CR) {
        float acc = 0.0f;
#pragma unroll 8
        for (int c = 0; c < C; ++c) {
            acc += s[c] * w1[c * CR + t];
        }
        h[t] = fminf(fmaxf(acc, 0.0f), 6.0f);
    }
    __syncthreads();

    float acc = 0.0f;
#pragma unroll
    for (int r = 0; r < CR; ++r) {
        acc += h[r] * w2[r * C + t];
    }
    g_gate[b * C + t] = fminf(fmaxf(acc + 3.0f, 0.0f), 6.0f) * (1.0f / 6.0f);
}

// ---------------------------------------------------------------------------
// mul_kernel: grid = (CHUNKS, BATCH) = 6272 blocks, 256 threads.
// Plain v8 loads of x (expected L2 hits — pinned evict_last by gap).
// WRITE-THROUGH stores (__stwt): out never allocates in L2, so the write
// stream cannot evict x. Warp writes 1024B contiguous = full 128B lines.
// ---------------------------------------------------------------------------
__global__ __launch_bounds__(256) void mul_kernel(const float* __restrict__ x,
                                                  float* __restrict__ out)
{
    const int chunk = blockIdx.x;
    const int b     = blockIdx.y;
    const int tid   = threadIdx.x;
    const int c8    = tid & (NG - 1);
    const int pr    = tid >> 5;

    float g[8];
    {
        const float4 ga = __ldca(&((const float4*)g_gate)[b * (C / 4) + c8 * 2]);
        const float4 gb = __ldca(&((const float4*)g_gate)[b * (C / 4) + c8 * 2 + 1]);
        g[0] = ga.x; g[1] = ga.y; g[2] = ga.z; g[3] = ga.w;
        g[4] = gb.x; g[5] = gb.y; g[6] = gb.z; g[7] = gb.w;
    }

    const size_t off = ((size_t)(b * HW + chunk * PPC + pr)) * C + c8 * 8;
    const float* xp = x + off;
    float*       op = out + off;

    uint32_t u0[8], u1[8];
    ld256(xp,                 u0);
    ld256(xp + (size_t)8 * C, u1);

    float4 a0, a1, b0, b1;
    a0.x = __uint_as_float(u0[0]) * g[0];
    a0.y = __uint_as_float(u0[1]) * g[1];
    a0.z = __uint_as_float(u0[2]) * g[2];
    a0.w = __uint_as_float(u0[3]) * g[3];
    a1.x = __uint_as_float(u0[4]) * g[4];
    a1.y = __uint_as_float(u0[5]) * g[5];
    a1.z = __uint_as_float(u0[6]) * g[6];
    a1.w = __uint_as_float(u0[7]) * g[7];
    b0.x = __uint_as_float(u1[0]) * g[0];
    b0.y = __uint_as_float(u1[1]) * g[1];
    b0.z = __uint_as_float(u1[2]) * g[2];
    b0.w = __uint_as_float(u1[3]) * g[3];
    b1.x = __uint_as_float(u1[4]) * g[4];
    b1.y = __uint_as_float(u1[5]) * g[5];
    b1.z = __uint_as_float(u1[6]) * g[6];
    b1.w = __uint_as_float(u1[7]) * g[7];

    // write-through: no L2 allocation for the out stream
    __stwt((float4*)op,                     a0);
    __stwt((float4*)(op + 4),               a1);
    __stwt((float4*)(op + (size_t)8 * C),     b0);
    __stwt((float4*)(op + (size_t)8 * C + 4), b1);
}

extern "C" void kernel_launch(void* const* d_in, const int* in_sizes, int n_in,
                              void* d_out, int out_size) {
    const float* x  = (const float*)d_in[0];
    const float* w1 = (const float*)d_in[1];
    const float* w2 = (const float*)d_in[2];
    float* out      = (float*)d_out;

    dim3 grid(CHUNKS, BATCH);
    gap_kernel<<<grid, 256>>>(x);
    fc_kernel<<<BATCH, 256>>>(w1, w2);
    mul_kernel<<<grid, 256>>>(x, out);
}